// round 4
// baseline (speedup 1.0000x reference)
#include <cuda_runtime.h>
#include <math.h>
#include <stdint.h>

#define TB 256
#define TT 200
#define TV 16
#define TN 64
#define TG 1024   // V*N
#define TK 1040   // V*(N+1)
#define NCTA 128
#define RTHREADS 256

__device__ float g_xT[TT][TV][TB];
__device__ float g_hsT[TT][TG][TB];
__device__ float g_aunT[TT][TV][TB];
__device__ float g_inv[TV][TB];
__device__ float g_gT[TG][TB];
__device__ unsigned g_bar;

typedef unsigned long long ull;
__device__ __forceinline__ ull pk2(float lo, float hi) {
    ull r; asm("mov.b64 %0, {%1, %2};" : "=l"(r) : "f"(lo), "f"(hi)); return r;
}
__device__ __forceinline__ void upk2(ull v, float& lo, float& hi) {
    asm("mov.b64 {%0, %1}, %2;" : "=f"(lo), "=f"(hi) : "l"(v));
}
__device__ __forceinline__ void fma2(ull& d, ull a, ull b) {
    asm("fma.rn.f32x2 %0, %1, %2, %0;" : "+l"(d) : "l"(a), "l"(b));
}

__global__ void k_xT(const float* __restrict__ x) {
    int t = blockIdx.x >> 4, v = blockIdx.x & 15, b = threadIdx.x;
    g_xT[t][v][b] = x[(size_t)b * (TT * TV) + t * TV + v];
    if (blockIdx.x == 0 && threadIdx.x == 0) g_bar = 0u;
}

// 12 weights (3 LDS.128) x 2 batch inputs -> 12 fma2
__device__ __forceinline__ void body(float i0, float i1, const float* wr, ull* a0, ull* a1) {
    ull d0 = pk2(i0, i0), d1 = pk2(i1, i1);
    ulonglong2 wA = *reinterpret_cast<const ulonglong2*>(wr);
    ulonglong2 wB = *reinterpret_cast<const ulonglong2*>(wr + 4);
    ulonglong2 wC = *reinterpret_cast<const ulonglong2*>(wr + 8);
    fma2(a0[0], wA.x, d0); fma2(a0[1], wA.y, d0);
    fma2(a0[2], wB.x, d0); fma2(a0[3], wB.y, d0);
    fma2(a0[4], wC.x, d0); fma2(a0[5], wC.y, d0);
    fma2(a1[0], wA.x, d1); fma2(a1[1], wA.y, d1);
    fma2(a1[2], wB.x, d1); fma2(a1[3], wB.y, d1);
    fma2(a1[4], wC.x, d1); fma2(a1[5], wC.y, d1);
}

__global__ void __launch_bounds__(RTHREADS, 1) k_recur(
    const float* __restrict__ U_j, const float* __restrict__ W_j, const float* __restrict__ b_j,
    const float* __restrict__ Wi, const float* __restrict__ bi,
    const float* __restrict__ Wf, const float* __restrict__ bf,
    const float* __restrict__ Wo, const float* __restrict__ bo)
{
    extern __shared__ float sm[];
    float* s_wg = sm;               // [1040][24], row r = u*3 + gate (u=0..7)
    float* s_wj = sm + TK * 24;     // [64][8]
    float* s_bg = s_wj + 512;       // 24 (r-order)
    float* s_bj = s_bg + 24;        // 8
    float* s_uu = s_bj + 8;         // 8

    const int tid = threadIdx.x, cta = blockIdx.x;
    const int g0 = cta * 8, v = g0 >> 6;
    const int n0 = g0 & 63;
    const int b = tid & 127, half = tid >> 7;

    for (int e = tid; e < TK * 24; e += RTHREADS) {
        int k = e / 24, r = e - k * 24;
        int u = r / 3, gate = r - 3 * u;
        const float* W = (gate == 0) ? Wi : (gate == 1) ? Wf : Wo;
        s_wg[e] = W[(size_t)(g0 + u) * TK + k];
    }
    for (int e = tid; e < 512; e += RTHREADS)
        s_wj[e] = W_j[v * TN * TN + (e >> 3) * TN + (n0 + (e & 7))];
    if (tid < 24) {
        int u = tid / 3, gate = tid - 3 * u;
        s_bg[tid] = ((gate == 0) ? bi : (gate == 1) ? bf : bo)[g0 + u];
    }
    if (tid < 8) {
        s_bj[tid] = b_j[v * TN + n0 + tid];
        s_uu[tid] = U_j[v * TN + n0 + tid];
    }
    __syncthreads();

    float c0[4] = {0.f, 0.f, 0.f, 0.f};
    float c1[4] = {0.f, 0.f, 0.f, 0.f};

    for (int t = 0; t < TT; ++t) {
        ull a0[6], a1[6];
        #pragma unroll
        for (int p = 0; p < 6; ++p) {
            ull bb = pk2(s_bg[12 * half + 2 * p], s_bg[12 * half + 2 * p + 1]);
            a0[p] = bb; a1[p] = bb;
        }
        const float* xt = &g_xT[t][0][0];
        float xv0 = xt[v * TB + b], xv1 = xt[v * TB + b + 128];
        ull j0[2], j1[2];
        #pragma unroll
        for (int q = 0; q < 2; ++q) {
            int u0 = 4 * half + 2 * q, u1 = u0 + 1;
            j0[q] = pk2(s_bj[u0] + xv0 * s_uu[u0], s_bj[u1] + xv0 * s_uu[u1]);
            j1[q] = pk2(s_bj[u0] + xv1 * s_uu[u0], s_bj[u1] + xv1 * s_uu[u1]);
        }

        #pragma unroll
        for (int k = 0; k < TV; ++k) {
            float i0 = xt[k * TB + b], i1 = xt[k * TB + b + 128];
            body(i0, i1, s_wg + k * 24 + 12 * half, a0, a1);
        }

        if (t > 0) {
            const float* hp = &g_hsT[t - 1][0][0];
            #pragma unroll 4
            for (int k = 0; k < TG; ++k) {
                float i0 = hp[k * TB + b], i1 = hp[k * TB + b + 128];
                body(i0, i1, s_wg + (TV + k) * 24 + 12 * half, a0, a1);
            }
            const float* hv = hp + (size_t)v * TN * TB;
            #pragma unroll 4
            for (int m = 0; m < TN; ++m) {
                float i0 = hv[m * TB + b], i1 = hv[m * TB + b + 128];
                ulonglong2 w = *reinterpret_cast<const ulonglong2*>(s_wj + m * 8 + 4 * half);
                ull d0 = pk2(i0, i0), d1 = pk2(i1, i1);
                fma2(j0[0], w.x, d0); fma2(j0[1], w.y, d0);
                fma2(j1[0], w.x, d1); fma2(j1[1], w.y, d1);
            }
        }

        float* ho = &g_hsT[t][0][0];
        #pragma unroll
        for (int lu = 0; lu < 4; ++lu) {
            const int ri = 3 * lu, rf = ri + 1, ro = ri + 2;
            float lo, hi;
            float zi0, zf0, zo0, zi1, zf1, zo1, zj0, zj1;
            upk2(a0[ri >> 1], lo, hi); zi0 = (ri & 1) ? hi : lo;
            upk2(a0[rf >> 1], lo, hi); zf0 = (rf & 1) ? hi : lo;
            upk2(a0[ro >> 1], lo, hi); zo0 = (ro & 1) ? hi : lo;
            upk2(a1[ri >> 1], lo, hi); zi1 = (ri & 1) ? hi : lo;
            upk2(a1[rf >> 1], lo, hi); zf1 = (rf & 1) ? hi : lo;
            upk2(a1[ro >> 1], lo, hi); zo1 = (ro & 1) ? hi : lo;
            upk2(j0[lu >> 1], lo, hi); zj0 = (lu & 1) ? hi : lo;
            upk2(j1[lu >> 1], lo, hi); zj1 = (lu & 1) ? hi : lo;

            float iv0 = 1.f / (1.f + expf(-zi0));
            float fv0 = 1.f / (1.f + expf(-zf0));
            float ov0 = 1.f / (1.f + expf(-zo0));
            float jv0 = tanhf(zj0);
            float iv1 = 1.f / (1.f + expf(-zi1));
            float fv1 = 1.f / (1.f + expf(-zf1));
            float ov1 = 1.f / (1.f + expf(-zo1));
            float jv1 = tanhf(zj1);

            float cn0 = c0[lu] * fv0 + iv0 * jv0;
            float cn1 = c1[lu] * fv1 + iv1 * jv1;
            c0[lu] = cn0; c1[lu] = cn1;
            size_t row = (size_t)(g0 + 4 * half + lu) * TB;
            ho[row + b]       = ov0 * tanhf(cn0);
            ho[row + b + 128] = ov1 * tanhf(cn1);
        }

        __syncthreads();
        if (tid == 0) {
            __threadfence();
            atomicAdd(&g_bar, 1u);
            unsigned target = (unsigned)(t + 1) * gridDim.x;
            while (*((volatile unsigned*)&g_bar) < target) { }
            __threadfence();
        }
        __syncthreads();
    }
}

__global__ void k_alphaA(const float* __restrict__ Fa, const float* __restrict__ Fab) {
    __shared__ float fa[TN]; __shared__ float fabv;
    int v = blockIdx.x, t0 = blockIdx.y * (TT / 8), b = threadIdx.x;
    if (threadIdx.x < TN) fa[threadIdx.x] = Fa[v * TN + threadIdx.x];
    if (threadIdx.x == 0) fabv = Fab[v];
    __syncthreads();
    for (int t = t0; t < t0 + TT / 8; ++t) {
        const float* hr = &g_hsT[t][v * TN][0];
        float ap = fabv;
        #pragma unroll 8
        for (int n = 0; n < TN; ++n) ap += hr[n * TB + b] * fa[n];
        g_aunT[t][v][b] = expf(tanhf(ap));
    }
}

__global__ void k_alphaInv() {
    int v = blockIdx.x, b = threadIdx.x;
    float s = 0.f;
    for (int t = 0; t < TT; ++t) s += g_aunT[t][v][b];
    g_inv[v][b] = 1.f / s;
}

__global__ void k_gn() {
    int v = blockIdx.x, nc = blockIdx.y * 4, b = threadIdx.x;
    float a0 = 0.f, a1 = 0.f, a2 = 0.f, a3 = 0.f;
    for (int t = 0; t < TT; ++t) {
        float au = g_aunT[t][v][b];
        const float* hr = &g_hsT[t][v * TN + nc][0];
        a0 += au * hr[0 * TB + b]; a1 += au * hr[1 * TB + b];
        a2 += au * hr[2 * TB + b]; a3 += au * hr[3 * TB + b];
    }
    float inv = g_inv[v][b];
    g_gT[v*TN+nc+0][b] = a0*inv; g_gT[v*TN+nc+1][b] = a1*inv;
    g_gT[v*TN+nc+2][b] = a2*inv; g_gT[v*TN+nc+3][b] = a3*inv;
}

__global__ void k_alphaOut(float* __restrict__ out) {
    int t = blockIdx.x, b = threadIdx.x;
    float* ao = out + TB;
    #pragma unroll
    for (int v = 0; v < TV; ++v)
        ao[((size_t)b * TT + t) * TV + v] = g_aunT[t][v][b] * g_inv[v][b];
}

__global__ void k_final(const float* __restrict__ Fbw, const float* __restrict__ Fbb,
                        const float* __restrict__ Phw, const float* __restrict__ Phb,
                        float* __restrict__ out) {
    __shared__ float phi[2 * TN], fbw[2 * TN];
    __shared__ float phib, fbb;
    int b = threadIdx.x;
    if (threadIdx.x < 2 * TN) { phi[threadIdx.x] = Phw[threadIdx.x]; fbw[threadIdx.x] = Fbw[threadIdx.x]; }
    if (threadIdx.x == 0) { phib = Phb[0]; fbb = Fbb[0]; }
    __syncthreads();
    float mu[TV], bu[TV], bs = 0.f;
    #pragma unroll
    for (int v = 0; v < TV; ++v) {
        const float* gr = &g_gT[v * TN][0];
        const float* hr = &g_hsT[TT - 1][v * TN][0];
        float m_ = phib, p_ = fbb;
        #pragma unroll 8
        for (int n = 0; n < TN; ++n) {
            float gv = gr[n * TB + b], hv = hr[n * TB + b];
            m_ += gv * phi[n] + hv * phi[TN + n];
            p_ += gv * fbw[n] + hv * fbw[TN + n];
        }
        mu[v] = m_;
        float e = expf(tanhf(p_));
        bu[v] = e; bs += e;
    }
    float ib = 1.f / bs, mean = 0.f;
    float* bout = out + TB + (size_t)TB * TT * TV;
    #pragma unroll
    for (int v = 0; v < TV; ++v) {
        float be = bu[v] * ib;
        mean += be * mu[v];
        bout[(size_t)b * TV + v] = be;
    }
    out[b] = mean;
}

extern "C" void kernel_launch(void* const* d_in, const int* in_sizes, int n_in,
                              void* d_out, int out_size) {
    const float* x    = (const float*)d_in[0];
    const float* U_j  = (const float*)d_in[1];
    const float* W_j  = (const float*)d_in[2];
    const float* b_j  = (const float*)d_in[3];
    const float* Wi   = (const float*)d_in[4];
    const float* bi   = (const float*)d_in[5];
    const float* Wf   = (const float*)d_in[6];
    const float* bf   = (const float*)d_in[7];
    const float* Wo   = (const float*)d_in[8];
    const float* bo   = (const float*)d_in[9];
    const float* Fa   = (const float*)d_in[10];
    const float* Fab  = (const float*)d_in[11];
    const float* Fbw  = (const float*)d_in[12];
    const float* Fbb  = (const float*)d_in[13];
    const float* Phw  = (const float*)d_in[14];
    const float* Phb  = (const float*)d_in[15];
    float* out = (float*)d_out;

    static const size_t SMEM = (size_t)(TK * 24 + 512 + 24 + 8 + 8) * sizeof(float);
    cudaFuncSetAttribute(k_recur, cudaFuncAttributeMaxDynamicSharedMemorySize, (int)SMEM);

    k_xT<<<TT * TV, TB>>>(x);
    k_recur<<<NCTA, RTHREADS, SMEM>>>(U_j, W_j, b_j, Wi, bi, Wf, bf, Wo, bo);
    k_alphaA<<<dim3(TV, 8), TB>>>(Fa, Fab);
    k_alphaInv<<<TV, TB>>>();
    k_gn<<<dim3(TV, TV), TB>>>();
    k_alphaOut<<<TT, TB>>>(out);
    k_final<<<1, TB>>>(Fbw, Fbb, Phw, Phb, out);
}

// round 6
// speedup vs baseline: 1.5488x; 1.5488x over previous
#include <cuda_runtime.h>
#include <math.h>
#include <stdint.h>

#define TB 256
#define TT 200
#define TV 16
#define TN 64
#define TG 1024   // V*N
#define TK 1040   // V*(N+1)
#define NCTA 128
#define RTHREADS 256

__device__ float g_xT[TT][TV][TB];
__device__ float g_hsT[TT][TG][TB];
__device__ float g_aunT[TT][TV][TB];
__device__ float g_inv[TV][TB];
__device__ float g_gT[TG][TB];
__device__ unsigned g_bar;

typedef unsigned long long ull;
__device__ __forceinline__ ull pk2(float lo, float hi) {
    ull r; asm("mov.b64 %0, {%1, %2};" : "=l"(r) : "f"(lo), "f"(hi)); return r;
}
__device__ __forceinline__ void upk2(ull v, float& lo, float& hi) {
    asm("mov.b64 {%0, %1}, %2;" : "=f"(lo), "=f"(hi) : "l"(v));
}
__device__ __forceinline__ void fma2(ull& d, ull a, ull b) {
    asm("fma.rn.f32x2 %0, %1, %2, %0;" : "+l"(d) : "l"(a), "l"(b));
}

__global__ void k_xT(const float* __restrict__ x) {
    int t = blockIdx.x >> 4, v = blockIdx.x & 15, b = threadIdx.x;
    g_xT[t][v][b] = x[(size_t)b * (TT * TV) + t * TV + v];
    if (blockIdx.x == 0 && threadIdx.x == 0) g_bar = 0u;
}

// 12 weights (3 LDS.128) x 2 batch inputs -> 12 fma2
__device__ __forceinline__ void body(float i0, float i1, const float* wr, ull* a0, ull* a1) {
    ull d0 = pk2(i0, i0), d1 = pk2(i1, i1);
    ulonglong2 wA = *reinterpret_cast<const ulonglong2*>(wr);
    ulonglong2 wB = *reinterpret_cast<const ulonglong2*>(wr + 4);
    ulonglong2 wC = *reinterpret_cast<const ulonglong2*>(wr + 8);
    fma2(a0[0], wA.x, d0); fma2(a0[1], wA.y, d0);
    fma2(a0[2], wB.x, d0); fma2(a0[3], wB.y, d0);
    fma2(a0[4], wC.x, d0); fma2(a0[5], wC.y, d0);
    fma2(a1[0], wA.x, d1); fma2(a1[1], wA.y, d1);
    fma2(a1[2], wB.x, d1); fma2(a1[3], wB.y, d1);
    fma2(a1[4], wC.x, d1); fma2(a1[5], wC.y, d1);
}

__global__ void __launch_bounds__(RTHREADS, 1) k_recur(
    const float* __restrict__ U_j, const float* __restrict__ W_j, const float* __restrict__ b_j,
    const float* __restrict__ Wi, const float* __restrict__ bi,
    const float* __restrict__ Wf, const float* __restrict__ bf,
    const float* __restrict__ Wo, const float* __restrict__ bo)
{
    extern __shared__ float sm[];
    float* s_wg = sm;               // [1040][24], row r = u*3 + gate (u=0..7)
    float* s_wj = sm + TK * 24;     // [64][8]
    float* s_bg = s_wj + 512;       // 24 (r-order)
    float* s_bj = s_bg + 24;        // 8
    float* s_uu = s_bj + 8;         // 8

    const int tid = threadIdx.x, cta = blockIdx.x;
    const int g0 = cta * 8, v = g0 >> 6;
    const int n0 = g0 & 63;
    const int b = tid & 127, half = tid >> 7;

    for (int e = tid; e < TK * 24; e += RTHREADS) {
        int k = e / 24, r = e - k * 24;
        int u = r / 3, gate = r - 3 * u;
        const float* W = (gate == 0) ? Wi : (gate == 1) ? Wf : Wo;
        s_wg[e] = W[(size_t)(g0 + u) * TK + k];
    }
    for (int e = tid; e < 512; e += RTHREADS)
        s_wj[e] = W_j[v * TN * TN + (e >> 3) * TN + (n0 + (e & 7))];
    if (tid < 24) {
        int u = tid / 3, gate = tid - 3 * u;
        s_bg[tid] = ((gate == 0) ? bi : (gate == 1) ? bf : bo)[g0 + u];
    }
    if (tid < 8) {
        s_bj[tid] = b_j[v * TN + n0 + tid];
        s_uu[tid] = U_j[v * TN + n0 + tid];
    }
    __syncthreads();

    float c0[4] = {0.f, 0.f, 0.f, 0.f};
    float c1[4] = {0.f, 0.f, 0.f, 0.f};

    for (int t = 0; t < TT; ++t) {
        ull a0[6], a1[6];
        #pragma unroll
        for (int p = 0; p < 6; ++p) {
            ull bb = pk2(s_bg[12 * half + 2 * p], s_bg[12 * half + 2 * p + 1]);
            a0[p] = bb; a1[p] = bb;
        }
        const float* xt = &g_xT[t][0][0];
        float xv0 = xt[v * TB + b], xv1 = xt[v * TB + b + 128];
        ull j0[2], j1[2];
        #pragma unroll
        for (int q = 0; q < 2; ++q) {
            int u0 = 4 * half + 2 * q, u1 = u0 + 1;
            j0[q] = pk2(s_bj[u0] + xv0 * s_uu[u0], s_bj[u1] + xv0 * s_uu[u1]);
            j1[q] = pk2(s_bj[u0] + xv1 * s_uu[u0], s_bj[u1] + xv1 * s_uu[u1]);
        }

        #pragma unroll
        for (int k = 0; k < TV; ++k) {
            float i0 = xt[k * TB + b], i1 = xt[k * TB + b + 128];
            body(i0, i1, s_wg + k * 24 + 12 * half, a0, a1);
        }

        if (t > 0) {
            const float* hp = &g_hsT[t - 1][0][0];
            // 8-deep software pipeline: 16 LDGs in flight
            float n0b[8], n1b[8];
            #pragma unroll
            for (int kk = 0; kk < 8; ++kk) {
                n0b[kk] = hp[kk * TB + b];
                n1b[kk] = hp[kk * TB + b + 128];
            }
            for (int k = 0; k < TG; k += 8) {
                float cur0[8], cur1[8];
                #pragma unroll
                for (int kk = 0; kk < 8; ++kk) { cur0[kk] = n0b[kk]; cur1[kk] = n1b[kk]; }
                if (k + 8 < TG) {
                    #pragma unroll
                    for (int kk = 0; kk < 8; ++kk) {
                        n0b[kk] = hp[(k + 8 + kk) * TB + b];
                        n1b[kk] = hp[(k + 8 + kk) * TB + b + 128];
                    }
                }
                #pragma unroll
                for (int kk = 0; kk < 8; ++kk)
                    body(cur0[kk], cur1[kk], s_wg + (TV + k + kk) * 24 + 12 * half, a0, a1);
            }
            // block-diagonal j GEMM with same pipelining
            const float* hv = hp + (size_t)v * TN * TB;
            float p0[8], p1[8];
            #pragma unroll
            for (int kk = 0; kk < 8; ++kk) {
                p0[kk] = hv[kk * TB + b];
                p1[kk] = hv[kk * TB + b + 128];
            }
            for (int m = 0; m < TN; m += 8) {
                float q0[8], q1[8];
                #pragma unroll
                for (int kk = 0; kk < 8; ++kk) { q0[kk] = p0[kk]; q1[kk] = p1[kk]; }
                if (m + 8 < TN) {
                    #pragma unroll
                    for (int kk = 0; kk < 8; ++kk) {
                        p0[kk] = hv[(m + 8 + kk) * TB + b];
                        p1[kk] = hv[(m + 8 + kk) * TB + b + 128];
                    }
                }
                #pragma unroll
                for (int kk = 0; kk < 8; ++kk) {
                    ulonglong2 w = *reinterpret_cast<const ulonglong2*>(s_wj + (m + kk) * 8 + 4 * half);
                    ull d0 = pk2(q0[kk], q0[kk]), d1 = pk2(q1[kk], q1[kk]);
                    fma2(j0[0], w.x, d0); fma2(j0[1], w.y, d0);
                    fma2(j1[0], w.x, d1); fma2(j1[1], w.y, d1);
                }
            }
        }

        float* ho = &g_hsT[t][0][0];
        #pragma unroll
        for (int lu = 0; lu < 4; ++lu) {
            const int ri = 3 * lu, rf = ri + 1, ro = ri + 2;
            float lo, hi;
            float zi0, zf0, zo0, zi1, zf1, zo1, zj0, zj1;
            upk2(a0[ri >> 1], lo, hi); zi0 = (ri & 1) ? hi : lo;
            upk2(a0[rf >> 1], lo, hi); zf0 = (rf & 1) ? hi : lo;
            upk2(a0[ro >> 1], lo, hi); zo0 = (ro & 1) ? hi : lo;
            upk2(a1[ri >> 1], lo, hi); zi1 = (ri & 1) ? hi : lo;
            upk2(a1[rf >> 1], lo, hi); zf1 = (rf & 1) ? hi : lo;
            upk2(a1[ro >> 1], lo, hi); zo1 = (ro & 1) ? hi : lo;
            upk2(j0[lu >> 1], lo, hi); zj0 = (lu & 1) ? hi : lo;
            upk2(j1[lu >> 1], lo, hi); zj1 = (lu & 1) ? hi : lo;

            float iv0 = 1.f / (1.f + expf(-zi0));
            float fv0 = 1.f / (1.f + expf(-zf0));
            float ov0 = 1.f / (1.f + expf(-zo0));
            float jv0 = tanhf(zj0);
            float iv1 = 1.f / (1.f + expf(-zi1));
            float fv1 = 1.f / (1.f + expf(-zf1));
            float ov1 = 1.f / (1.f + expf(-zo1));
            float jv1 = tanhf(zj1);

            float cn0 = c0[lu] * fv0 + iv0 * jv0;
            float cn1 = c1[lu] * fv1 + iv1 * jv1;
            c0[lu] = cn0; c1[lu] = cn1;
            size_t row = (size_t)(g0 + 4 * half + lu) * TB;
            ho[row + b]       = ov0 * tanhf(cn0);
            ho[row + b + 128] = ov1 * tanhf(cn1);
        }

        __syncthreads();
        if (tid == 0) {
            __threadfence();
            atomicAdd(&g_bar, 1u);
            unsigned target = (unsigned)(t + 1) * gridDim.x;
            while (*((volatile unsigned*)&g_bar) < target) { }
            __threadfence();
        }
        __syncthreads();
    }
}

__global__ void k_alphaA(const float* __restrict__ Fa, const float* __restrict__ Fab) {
    __shared__ float fa[TN]; __shared__ float fabv;
    int v = blockIdx.x, t0 = blockIdx.y * 8, b = threadIdx.x;
    if (threadIdx.x < TN) fa[threadIdx.x] = Fa[v * TN + threadIdx.x];
    if (threadIdx.x == 0) fabv = Fab[v];
    __syncthreads();
    for (int t = t0; t < t0 + 8; ++t) {
        const float* hr = &g_hsT[t][v * TN][0];
        float ap = fabv;
        #pragma unroll 8
        for (int n = 0; n < TN; ++n) ap += hr[n * TB + b] * fa[n];
        g_aunT[t][v][b] = expf(tanhf(ap));
    }
}

__global__ void k_alphaInv() {
    int v = blockIdx.x, b = threadIdx.x;
    float s = 0.f;
    for (int t = 0; t < TT; ++t) s += g_aunT[t][v][b];
    g_inv[v][b] = 1.f / s;
}

__global__ void k_gn() {
    int v = blockIdx.x, nc = blockIdx.y * 2, b = threadIdx.x;
    float a0 = 0.f, a1 = 0.f;
    for (int t = 0; t < TT; ++t) {
        float au = g_aunT[t][v][b];
        const float* hr = &g_hsT[t][v * TN + nc][0];
        a0 += au * hr[0 * TB + b];
        a1 += au * hr[1 * TB + b];
    }
    float inv = g_inv[v][b];
    g_gT[v * TN + nc + 0][b] = a0 * inv;
    g_gT[v * TN + nc + 1][b] = a1 * inv;
}

__global__ void k_alphaOut(float* __restrict__ out) {
    int t = blockIdx.x, b = threadIdx.x;
    float* ao = out + TB;
    #pragma unroll
    for (int v = 0; v < TV; ++v)
        ao[((size_t)b * TT + t) * TV + v] = g_aunT[t][v][b] * g_inv[v][b];
}

__global__ void k_final(const float* __restrict__ Fbw, const float* __restrict__ Fbb,
                        const float* __restrict__ Phw, const float* __restrict__ Phb,
                        float* __restrict__ out) {
    __shared__ float phi[2 * TN], fbw[2 * TN];
    __shared__ float phib, fbb;
    int b = threadIdx.x;
    if (threadIdx.x < 2 * TN) { phi[threadIdx.x] = Phw[threadIdx.x]; fbw[threadIdx.x] = Fbw[threadIdx.x]; }
    if (threadIdx.x == 0) { phib = Phb[0]; fbb = Fbb[0]; }
    __syncthreads();
    float mu[TV], bu[TV], bs = 0.f;
    #pragma unroll
    for (int v = 0; v < TV; ++v) {
        const float* gr = &g_gT[v * TN][0];
        const float* hr = &g_hsT[TT - 1][v * TN][0];
        float m_ = phib, p_ = fbb;
        #pragma unroll 8
        for (int n = 0; n < TN; ++n) {
            float gv = gr[n * TB + b], hv = hr[n * TB + b];
            m_ += gv * phi[n] + hv * phi[TN + n];
            p_ += gv * fbw[n] + hv * fbw[TN + n];
        }
        mu[v] = m_;
        float e = expf(tanhf(p_));
        bu[v] = e; bs += e;
    }
    float ib = 1.f / bs, mean = 0.f;
    float* bout = out + TB + (size_t)TB * TT * TV;
    #pragma unroll
    for (int v = 0; v < TV; ++v) {
        float be = bu[v] * ib;
        mean += be * mu[v];
        bout[(size_t)b * TV + v] = be;
    }
    out[b] = mean;
}

extern "C" void kernel_launch(void* const* d_in, const int* in_sizes, int n_in,
                              void* d_out, int out_size) {
    const float* x    = (const float*)d_in[0];
    const float* U_j  = (const float*)d_in[1];
    const float* W_j  = (const float*)d_in[2];
    const float* b_j  = (const float*)d_in[3];
    const float* Wi   = (const float*)d_in[4];
    const float* bi   = (const float*)d_in[5];
    const float* Wf   = (const float*)d_in[6];
    const float* bf   = (const float*)d_in[7];
    const float* Wo   = (const float*)d_in[8];
    const float* bo   = (const float*)d_in[9];
    const float* Fa   = (const float*)d_in[10];
    const float* Fab  = (const float*)d_in[11];
    const float* Fbw  = (const float*)d_in[12];
    const float* Fbb  = (const float*)d_in[13];
    const float* Phw  = (const float*)d_in[14];
    const float* Phb  = (const float*)d_in[15];
    float* out = (float*)d_out;

    static const size_t SMEM = (size_t)(TK * 24 + 512 + 24 + 8 + 8) * sizeof(float);
    cudaFuncSetAttribute(k_recur, cudaFuncAttributeMaxDynamicSharedMemorySize, (int)SMEM);

    k_xT<<<TT * TV, TB>>>(x);
    k_recur<<<NCTA, RTHREADS, SMEM>>>(U_j, W_j, b_j, Wi, bi, Wf, bf, Wo, bo);
    k_alphaA<<<dim3(TV, 25), TB>>>(Fa, Fab);
    k_alphaInv<<<TV, TB>>>();
    k_gn<<<dim3(TV, 32), TB>>>();
    k_alphaOut<<<TT, TB>>>(out);
    k_final<<<1, TB>>>(Fbw, Fbb, Phw, Phb, out);
}

// round 7
// speedup vs baseline: 2.4013x; 1.5505x over previous
#include <cuda_runtime.h>
#include <cuda_bf16.h>
#include <math.h>
#include <stdint.h>

#define TB 256
#define TT 200
#define TV 16
#define TN 64
#define TG 1024   // V*N
#define TK 1040   // V*(N+1)
#define NCTA 128
#define NGEMM 96
#define RTHREADS 256

__device__ float g_xT[TT][TV][TB];
__device__ float g_hsT[TT][TG][TB];
__device__ float g_aunT[TT][TV][TB];
__device__ float g_inv[TV][TB];
__device__ float g_gT[TG][TB];
__device__ float g_Z[3 * TG * TB];                       // gate pre-activations (h-part)
__device__ __align__(16) uint32_t g_hA_hi[64 * 16 * 32 * 4];   // A fragments (h) hi
__device__ __align__(16) uint32_t g_hA_lo[64 * 16 * 32 * 4];   // A fragments (h) lo
__device__ __align__(16) uint32_t g_WB_hi[64 * 384 * 32 * 2];  // B fragments (W) hi
__device__ __align__(16) uint32_t g_WB_lo[64 * 384 * 32 * 2];  // B fragments (W) lo
__device__ unsigned g_bar;

__device__ __forceinline__ void mma_bf16(float* d, const uint32_t* a, const uint32_t* b) {
    asm volatile(
        "mma.sync.aligned.m16n8k16.row.col.f32.bf16.bf16.f32 "
        "{%0,%1,%2,%3}, {%4,%5,%6,%7}, {%8,%9}, {%0,%1,%2,%3};"
        : "+f"(d[0]), "+f"(d[1]), "+f"(d[2]), "+f"(d[3])
        : "r"(a[0]), "r"(a[1]), "r"(a[2]), "r"(a[3]), "r"(b[0]), "r"(b[1]));
}

__device__ __forceinline__ uint32_t pack_bf(float v0, float v1) {
    __nv_bfloat162 t = { __float2bfloat16(v0), __float2bfloat16(v1) };
    return *reinterpret_cast<uint32_t*>(&t);
}

__global__ void k_xT(const float* __restrict__ x) {
    int t = blockIdx.x >> 4, v = blockIdx.x & 15, b = threadIdx.x;
    g_xT[t][v][b] = x[(size_t)b * (TT * TV) + t * TV + v];
    if (blockIdx.x == 0 && threadIdx.x == 0) g_bar = 0u;
}

// precompute bf16 hi/lo B fragments of the gate weights (h-part cols 16..1039)
__global__ void k_wfrag(const float* __restrict__ Wi, const float* __restrict__ Wf,
                        const float* __restrict__ Wo) {
    int nt = blockIdx.x, kc = blockIdx.y;
    int l = threadIdx.x & 31, reg = threadIdx.x >> 5;
    int n = nt * 8 + (l >> 2);
    int gate = n >> 10, u = n & 1023;
    const float* W = (gate == 0) ? Wi : (gate == 1) ? Wf : Wo;
    int k0 = kc * 16 + (l & 3) * 2 + reg * 8;
    float v0 = W[(size_t)u * TK + 16 + k0];
    float v1 = W[(size_t)u * TK + 16 + k0 + 1];
    __nv_bfloat16 h0 = __float2bfloat16(v0), h1 = __float2bfloat16(v1);
    float r0 = v0 - __bfloat162float(h0), r1 = v1 - __bfloat162float(h1);
    __nv_bfloat162 ph = { h0, h1 };
    size_t idx = ((size_t)(kc * 384 + nt) * 32 + l) * 2 + reg;
    g_WB_hi[idx] = *reinterpret_cast<uint32_t*>(&ph);
    g_WB_lo[idx] = pack_bf(r0, r1);
}

__global__ void __launch_bounds__(RTHREADS, 1) k_recur(
    const float* __restrict__ U_j, const float* __restrict__ W_j, const float* __restrict__ b_j,
    const float* __restrict__ Wi, const float* __restrict__ bi,
    const float* __restrict__ Wf, const float* __restrict__ bf,
    const float* __restrict__ Wo, const float* __restrict__ bo)
{
    __shared__ float s_wgx[16 * 24];   // x-part weights [k][r], r = gate*8+ul
    __shared__ float s_wj[64 * 8];
    __shared__ float s_bg[24];         // gate biases, r-order
    __shared__ float s_bj[8];
    __shared__ float s_uu[8];

    const int tid = threadIdx.x, cta = blockIdx.x;
    const int lane = tid & 31, wid = tid >> 5;
    const int g0 = cta * 8, v = g0 >> 6, n0 = g0 & 63;
    const int b = tid;

    for (int e = tid; e < 16 * 24; e += RTHREADS) {
        int k = e / 24, r = e - k * 24, g = r >> 3, ul = r & 7;
        const float* W = (g == 0) ? Wi : (g == 1) ? Wf : Wo;
        s_wgx[e] = W[(size_t)(g0 + ul) * TK + k];
    }
    for (int e = tid; e < 512; e += RTHREADS)
        s_wj[e] = W_j[v * TN * TN + (e >> 3) * TN + (n0 + (e & 7))];
    if (tid < 24) {
        int g = tid >> 3, ul = tid & 7;
        s_bg[tid] = ((g == 0) ? bi : (g == 1) ? bf : bo)[g0 + ul];
    }
    if (tid < 8) { s_bj[tid] = b_j[v * TN + n0 + tid]; s_uu[tid] = U_j[v * TN + n0 + tid]; }
    __syncthreads();

    // epilogue fragment-write constants (thread = batch column b)
    const int kc_e = g0 >> 4;
    const int mt_e = b >> 4, r_e = b & 15;
    const int reg_e = ((r_e >> 3) & 1) | ((g0 & 8) ? 2 : 0);
    const int lane_e = (r_e & 7) * 4;

    float cc[8];
    #pragma unroll
    for (int u = 0; u < 8; ++u) cc[u] = 0.f;
    unsigned ph_cnt = 0;

    for (int t = 0; t < TT; ++t) {
        // ================= GEMM phase (96 CTAs, h-part of gates) =================
        if (t > 0 && cta < NGEMM) {
            float acc[2][4][4];
            #pragma unroll
            for (int i = 0; i < 2; ++i)
                #pragma unroll
                for (int j = 0; j < 4; ++j)
                    #pragma unroll
                    for (int q = 0; q < 4; ++q) acc[i][j][q] = 0.f;

            const uint4* __restrict__ Ah = (const uint4*)g_hA_hi;
            const uint4* __restrict__ Al = (const uint4*)g_hA_lo;
            const uint2* __restrict__ Bh = (const uint2*)g_WB_hi;
            const uint2* __restrict__ Bl = (const uint2*)g_WB_lo;
            const int mt0 = wid * 2, mt1 = mt0 + 1;
            const int ntb = cta * 4;

            uint4 ah0 = Ah[(0 * 16 + mt0) * 32 + lane];
            uint4 ah1 = Ah[(0 * 16 + mt1) * 32 + lane];
            uint4 al0 = Al[(0 * 16 + mt0) * 32 + lane];
            uint4 al1 = Al[(0 * 16 + mt1) * 32 + lane];
            uint2 bh[4], bl[4];
            #pragma unroll
            for (int j = 0; j < 4; ++j) {
                bh[j] = Bh[(size_t)(0 * 384 + ntb + j) * 32 + lane];
                bl[j] = Bl[(size_t)(0 * 384 + ntb + j) * 32 + lane];
            }

            #pragma unroll 2
            for (int kc = 0; kc < 64; ++kc) {
                uint4 nah0, nah1, nal0, nal1;
                uint2 nbh[4], nbl[4];
                if (kc < 63) {
                    int kn = kc + 1;
                    nah0 = Ah[(kn * 16 + mt0) * 32 + lane];
                    nah1 = Ah[(kn * 16 + mt1) * 32 + lane];
                    nal0 = Al[(kn * 16 + mt0) * 32 + lane];
                    nal1 = Al[(kn * 16 + mt1) * 32 + lane];
                    #pragma unroll
                    for (int j = 0; j < 4; ++j) {
                        nbh[j] = Bh[(size_t)(kn * 384 + ntb + j) * 32 + lane];
                        nbl[j] = Bl[(size_t)(kn * 384 + ntb + j) * 32 + lane];
                    }
                }
                #pragma unroll
                for (int j = 0; j < 4; ++j) {
                    mma_bf16(acc[0][j], (const uint32_t*)&ah0, (const uint32_t*)&bh[j]);
                    mma_bf16(acc[0][j], (const uint32_t*)&al0, (const uint32_t*)&bh[j]);
                    mma_bf16(acc[0][j], (const uint32_t*)&ah0, (const uint32_t*)&bl[j]);
                    mma_bf16(acc[1][j], (const uint32_t*)&ah1, (const uint32_t*)&bh[j]);
                    mma_bf16(acc[1][j], (const uint32_t*)&al1, (const uint32_t*)&bh[j]);
                    mma_bf16(acc[1][j], (const uint32_t*)&ah1, (const uint32_t*)&bl[j]);
                }
                if (kc < 63) {
                    ah0 = nah0; ah1 = nah1; al0 = nal0; al1 = nal1;
                    #pragma unroll
                    for (int j = 0; j < 4; ++j) { bh[j] = nbh[j]; bl[j] = nbl[j]; }
                }
            }
            // scatter D -> g_Z[n][b]
            #pragma unroll
            for (int i = 0; i < 2; ++i) {
                int b0 = (wid * 2 + i) * 16 + (lane >> 2);
                #pragma unroll
                for (int j = 0; j < 4; ++j) {
                    int nrow = (ntb + j) * 8 + (lane & 3) * 2;
                    g_Z[(size_t)nrow * TB + b0]           = acc[i][j][0];
                    g_Z[(size_t)(nrow + 1) * TB + b0]     = acc[i][j][1];
                    g_Z[(size_t)nrow * TB + b0 + 8]       = acc[i][j][2];
                    g_Z[(size_t)(nrow + 1) * TB + b0 + 8] = acc[i][j][3];
                }
            }
        }
        // barrier A (Z ready)
        __syncthreads();
        ++ph_cnt;
        if (tid == 0) {
            __threadfence(); atomicAdd(&g_bar, 1u);
            while (*((volatile unsigned*)&g_bar) < ph_cnt * NCTA) { }
            __threadfence();
        }
        __syncthreads();

        // ================= epilogue phase (all CTAs; thread = batch b) =================
        {
            float zz[24];
            #pragma unroll
            for (int r = 0; r < 24; ++r) zz[r] = s_bg[r];
            if (t > 0) {
                #pragma unroll
                for (int g = 0; g < 3; ++g)
                    #pragma unroll
                    for (int ul = 0; ul < 8; ++ul)
                        zz[g * 8 + ul] += g_Z[(size_t)(g * TG + g0 + ul) * TB + b];
            }
            const float* xt = &g_xT[t][0][0];
            #pragma unroll
            for (int k = 0; k < TV; ++k) {
                float xv = xt[k * TB + b];
                const float* wr = s_wgx + k * 24;
                #pragma unroll
                for (int r = 0; r < 24; ++r) zz[r] += xv * wr[r];
            }
            float xvo = xt[v * TB + b];
            float jac[8];
            #pragma unroll
            for (int u = 0; u < 8; ++u) jac[u] = s_bj[u] + xvo * s_uu[u];
            if (t > 0) {
                const float* hv = &g_hsT[t - 1][v * TN][0];
                #pragma unroll 8
                for (int m = 0; m < TN; ++m) {
                    float hm = hv[m * TB + b];
                    const float* wr = s_wj + m * 8;
                    #pragma unroll
                    for (int u = 0; u < 8; ++u) jac[u] += hm * wr[u];
                }
            }
            float hval[8];
            float* ho = &g_hsT[t][0][0];
            #pragma unroll
            for (int ul = 0; ul < 8; ++ul) {
                float zi = zz[ul], zf = zz[8 + ul], zo = zz[16 + ul];
                float iv = 1.f / (1.f + expf(-zi));
                float fv = 1.f / (1.f + expf(-zf));
                float ov = 1.f / (1.f + expf(-zo));
                float jv = tanhf(jac[ul]);
                float cn = cc[ul] * fv + iv * jv;
                cc[ul] = cn;
                hval[ul] = ov * tanhf(cn);
                ho[(size_t)(g0 + ul) * TB + b] = hval[ul];
            }
            // write bf16 hi/lo A-fragments for next step's GEMM
            #pragma unroll
            for (int p = 0; p < 4; ++p) {
                float v0 = hval[2 * p], v1 = hval[2 * p + 1];
                __nv_bfloat16 h0 = __float2bfloat16(v0), h1 = __float2bfloat16(v1);
                float q0 = v0 - __bfloat162float(h0), q1 = v1 - __bfloat162float(h1);
                __nv_bfloat162 ph = { h0, h1 };
                size_t idx = ((size_t)(kc_e * 16 + mt_e) * 32 + lane_e + p) * 4 + reg_e;
                g_hA_hi[idx] = *reinterpret_cast<uint32_t*>(&ph);
                g_hA_lo[idx] = pack_bf(q0, q1);
            }
        }
        // barrier B (h + fragments ready)
        __syncthreads();
        ++ph_cnt;
        if (tid == 0) {
            __threadfence(); atomicAdd(&g_bar, 1u);
            while (*((volatile unsigned*)&g_bar) < ph_cnt * NCTA) { }
            __threadfence();
        }
        __syncthreads();
    }
}

__global__ void k_alphaA(const float* __restrict__ Fa, const float* __restrict__ Fab) {
    __shared__ float fa[TN]; __shared__ float fabv;
    int v = blockIdx.x, t0 = blockIdx.y * 8, b = threadIdx.x;
    if (threadIdx.x < TN) fa[threadIdx.x] = Fa[v * TN + threadIdx.x];
    if (threadIdx.x == 0) fabv = Fab[v];
    __syncthreads();
    for (int t = t0; t < t0 + 8; ++t) {
        const float* hr = &g_hsT[t][v * TN][0];
        float ap = fabv;
        #pragma unroll 8
        for (int n = 0; n < TN; ++n) ap += hr[n * TB + b] * fa[n];
        g_aunT[t][v][b] = expf(tanhf(ap));
    }
}

__global__ void k_alphaInv() {
    int v = blockIdx.x, b = threadIdx.x;
    float s = 0.f;
    for (int t = 0; t < TT; ++t) s += g_aunT[t][v][b];
    g_inv[v][b] = 1.f / s;
}

__global__ void k_gn() {
    int v = blockIdx.x, nc = blockIdx.y * 2, b = threadIdx.x;
    float a0 = 0.f, a1 = 0.f;
    for (int t = 0; t < TT; ++t) {
        float au = g_aunT[t][v][b];
        const float* hr = &g_hsT[t][v * TN + nc][0];
        a0 += au * hr[0 * TB + b];
        a1 += au * hr[1 * TB + b];
    }
    float inv = g_inv[v][b];
    g_gT[v * TN + nc + 0][b] = a0 * inv;
    g_gT[v * TN + nc + 1][b] = a1 * inv;
}

__global__ void k_alphaOut(float* __restrict__ out) {
    int t = blockIdx.x, b = threadIdx.x;
    float* ao = out + TB;
    #pragma unroll
    for (int v = 0; v < TV; ++v)
        ao[((size_t)b * TT + t) * TV + v] = g_aunT[t][v][b] * g_inv[v][b];
}

__global__ void k_final(const float* __restrict__ Fbw, const float* __restrict__ Fbb,
                        const float* __restrict__ Phw, const float* __restrict__ Phb,
                        float* __restrict__ out) {
    __shared__ float phi[2 * TN], fbw[2 * TN];
    __shared__ float phib, fbb;
    int b = threadIdx.x;
    if (threadIdx.x < 2 * TN) { phi[threadIdx.x] = Phw[threadIdx.x]; fbw[threadIdx.x] = Fbw[threadIdx.x]; }
    if (threadIdx.x == 0) { phib = Phb[0]; fbb = Fbb[0]; }
    __syncthreads();
    float mu[TV], bu[TV], bs = 0.f;
    #pragma unroll
    for (int v = 0; v < TV; ++v) {
        const float* gr = &g_gT[v * TN][0];
        const float* hr = &g_hsT[TT - 1][v * TN][0];
        float m_ = phib, p_ = fbb;
        #pragma unroll 8
        for (int n = 0; n < TN; ++n) {
            float gv = gr[n * TB + b], hv = hr[n * TB + b];
            m_ += gv * phi[n] + hv * phi[TN + n];
            p_ += gv * fbw[n] + hv * fbw[TN + n];
        }
        mu[v] = m_;
        float e = expf(tanhf(p_));
        bu[v] = e; bs += e;
    }
    float ib = 1.f / bs, mean = 0.f;
    float* bout = out + TB + (size_t)TB * TT * TV;
    #pragma unroll
    for (int v = 0; v < TV; ++v) {
        float be = bu[v] * ib;
        mean += be * mu[v];
        bout[(size_t)b * TV + v] = be;
    }
    out[b] = mean;
}

extern "C" void kernel_launch(void* const* d_in, const int* in_sizes, int n_in,
                              void* d_out, int out_size) {
    const float* x    = (const float*)d_in[0];
    const float* U_j  = (const float*)d_in[1];
    const float* W_j  = (const float*)d_in[2];
    const float* b_j  = (const float*)d_in[3];
    const float* Wi   = (const float*)d_in[4];
    const float* bi   = (const float*)d_in[5];
    const float* Wf   = (const float*)d_in[6];
    const float* bf   = (const float*)d_in[7];
    const float* Wo   = (const float*)d_in[8];
    const float* bo   = (const float*)d_in[9];
    const float* Fa   = (const float*)d_in[10];
    const float* Fab  = (const float*)d_in[11];
    const float* Fbw  = (const float*)d_in[12];
    const float* Fbb  = (const float*)d_in[13];
    const float* Phw  = (const float*)d_in[14];
    const float* Phb  = (const float*)d_in[15];
    float* out = (float*)d_out;

    k_xT<<<TT * TV, TB>>>(x);
    k_wfrag<<<dim3(384, 64), 64>>>(Wi, Wf, Wo);
    k_recur<<<NCTA, RTHREADS>>>(U_j, W_j, b_j, Wi, bi, Wf, bf, Wo, bo);
    k_alphaA<<<dim3(TV, 25), TB>>>(Fa, Fab);
    k_alphaInv<<<TV, TB>>>();
    k_gn<<<dim3(TV, 32), TB>>>();
    k_alphaOut<<<TT, TB>>>(out);
    k_final<<<1, TB>>>(Fbw, Fbb, Phw, Phb, out);
}

// round 8
// speedup vs baseline: 4.1021x; 1.7082x over previous
#include <cuda_runtime.h>
#include <cuda_bf16.h>
#include <math.h>
#include <stdint.h>

#define TB 256
#define TT 200
#define TV 16
#define TN 64
#define TG 1024   // V*N
#define TK 1040   // V*(N+1)
#define NCTA 128
#define RTHREADS 256

__device__ float g_xT[TT][TV][TB];
__device__ float g_hsT[TT][TG][TB];
__device__ float g_aunT[TT][TV][TB];
__device__ float g_inv[TV][TB];
__device__ float g_gT[TG][TB];
__device__ __align__(16) uint32_t g_hA_hi[64 * 16 * 32 * 4];   // A fragments (h) hi
__device__ __align__(16) uint32_t g_hA_lo[64 * 16 * 32 * 4];   // A fragments (h) lo
__device__ __align__(16) uint32_t g_WB_hi[64 * 384 * 32 * 2];  // B fragments (W) hi
__device__ __align__(16) uint32_t g_WB_lo[64 * 384 * 32 * 2];  // B fragments (W) lo
__device__ unsigned g_bar;

__device__ __forceinline__ void mma_bf16(float* d, const uint32_t* a, const uint32_t* b) {
    asm volatile(
        "mma.sync.aligned.m16n8k16.row.col.f32.bf16.bf16.f32 "
        "{%0,%1,%2,%3}, {%4,%5,%6,%7}, {%8,%9}, {%0,%1,%2,%3};"
        : "+f"(d[0]), "+f"(d[1]), "+f"(d[2]), "+f"(d[3])
        : "r"(a[0]), "r"(a[1]), "r"(a[2]), "r"(a[3]), "r"(b[0]), "r"(b[1]));
}

__device__ __forceinline__ uint32_t pack_bf(float v0, float v1) {
    __nv_bfloat162 t = { __float2bfloat16(v0), __float2bfloat16(v1) };
    return *reinterpret_cast<uint32_t*>(&t);
}

__global__ void k_xT(const float* __restrict__ x) {
    int t = blockIdx.x >> 4, v = blockIdx.x & 15, b = threadIdx.x;
    g_xT[t][v][b] = x[(size_t)b * (TT * TV) + t * TV + v];
    if (blockIdx.x == 0 && threadIdx.x == 0) g_bar = 0u;
}

// precompute bf16 hi/lo B fragments of gate weights (h-part cols 16..1039)
__global__ void k_wfrag(const float* __restrict__ Wi, const float* __restrict__ Wf,
                        const float* __restrict__ Wo) {
    int nt = blockIdx.x, kc = blockIdx.y;
    int l = threadIdx.x & 31, reg = threadIdx.x >> 5;
    int n = nt * 8 + (l >> 2);
    int gate = n >> 10, u = n & 1023;
    const float* W = (gate == 0) ? Wi : (gate == 1) ? Wf : Wo;
    int k0 = kc * 16 + (l & 3) * 2 + reg * 8;
    float v0 = W[(size_t)u * TK + 16 + k0];
    float v1 = W[(size_t)u * TK + 16 + k0 + 1];
    __nv_bfloat16 h0 = __float2bfloat16(v0), h1 = __float2bfloat16(v1);
    float r0 = v0 - __bfloat162float(h0), r1 = v1 - __bfloat162float(h1);
    __nv_bfloat162 ph = { h0, h1 };
    size_t idx = ((size_t)(kc * 384 + nt) * 32 + l) * 2 + reg;
    g_WB_hi[idx] = *reinterpret_cast<uint32_t*>(&ph);
    g_WB_lo[idx] = pack_bf(r0, r1);
}

__global__ void __launch_bounds__(RTHREADS, 1) k_recur(
    const float* __restrict__ U_j, const float* __restrict__ W_j, const float* __restrict__ b_j,
    const float* __restrict__ Wi, const float* __restrict__ bi,
    const float* __restrict__ Wf, const float* __restrict__ bf,
    const float* __restrict__ Wo, const float* __restrict__ bo)
{
    __shared__ float s_wgx[16 * 24];   // x-part weights [k][r], r = gate*8+ul
    __shared__ float s_wj[64 * 8];
    __shared__ float s_bg[24];
    __shared__ float s_bj[8];
    __shared__ float s_uu[8];
    extern __shared__ uint32_t smdyn[];
    uint32_t* s_Bh = smdyn;                     // [3][64][32][2] = 12288 u32
    uint32_t* s_Bl = smdyn + 12288;             // 12288 u32
    float*    s_D  = (float*)(smdyn + 24576);   // [24][256]

    const int tid = threadIdx.x, cta = blockIdx.x;
    const int lane = tid & 31, wid = tid >> 5;
    const int g0 = cta * 8, v = g0 >> 6, n0 = g0 & 63;
    const int b = tid;

    // ---- one-time staging ----
    for (int e = tid; e < 16 * 24; e += RTHREADS) {
        int k = e / 24, r = e - k * 24, g = r >> 3, ul = r & 7;
        const float* W = (g == 0) ? Wi : (g == 1) ? Wf : Wo;
        s_wgx[e] = W[(size_t)(g0 + ul) * TK + k];
    }
    for (int e = tid; e < 512; e += RTHREADS)
        s_wj[e] = W_j[v * TN * TN + (e >> 3) * TN + (n0 + (e & 7))];
    if (tid < 24) {
        int g = tid >> 3, ul = tid & 7;
        s_bg[tid] = ((g == 0) ? bi : (g == 1) ? bf : bo)[g0 + ul];
    }
    if (tid < 8) { s_bj[tid] = b_j[v * TN + n0 + tid]; s_uu[tid] = U_j[v * TN + n0 + tid]; }
    // B fragments for this CTA's 24 N-rows: ntg = g*128 + cta, g = gate
    for (int e = tid; e < 12288; e += RTHREADS) {
        int reg = e & 1, l = (e >> 1) & 31, kc = (e >> 6) & 63, g = e >> 12;
        size_t src = ((size_t)(kc * 384 + g * 128 + cta) * 32 + l) * 2 + reg;
        s_Bh[e] = g_WB_hi[src];
        s_Bl[e] = g_WB_lo[src];
    }
    __syncthreads();

    // epilogue A-fragment write constants (thread = batch column b)
    const int kc_e = g0 >> 4;
    const int mt_e = b >> 4, r_e = b & 15;
    const int reg_e = ((r_e >> 3) & 1) | ((g0 & 8) ? 2 : 0);
    const int lane_e = (r_e & 7) * 4;

    float cc[8];
    #pragma unroll
    for (int u = 0; u < 8; ++u) cc[u] = 0.f;

    for (int t = 0; t < TT; ++t) {
        // ========== GEMM: this CTA's 24 N-rows x 256 batch, K=1024 ==========
        if (t > 0) {
            float acc[2][3][4];
            #pragma unroll
            for (int i = 0; i < 2; ++i)
                #pragma unroll
                for (int g = 0; g < 3; ++g)
                    #pragma unroll
                    for (int q = 0; q < 4; ++q) acc[i][g][q] = 0.f;

            const uint4* __restrict__ Ah = (const uint4*)g_hA_hi;
            const uint4* __restrict__ Al = (const uint4*)g_hA_lo;
            const int mt0 = wid * 2, mt1 = mt0 + 1;

            uint4 ah0 = Ah[(0 * 16 + mt0) * 32 + lane];
            uint4 ah1 = Ah[(0 * 16 + mt1) * 32 + lane];
            uint4 al0 = Al[(0 * 16 + mt0) * 32 + lane];
            uint4 al1 = Al[(0 * 16 + mt1) * 32 + lane];

            #pragma unroll 4
            for (int kc = 0; kc < 64; ++kc) {
                uint4 nah0, nah1, nal0, nal1;
                if (kc < 63) {
                    int kn = kc + 1;
                    nah0 = Ah[(kn * 16 + mt0) * 32 + lane];
                    nah1 = Ah[(kn * 16 + mt1) * 32 + lane];
                    nal0 = Al[(kn * 16 + mt0) * 32 + lane];
                    nal1 = Al[(kn * 16 + mt1) * 32 + lane];
                }
                #pragma unroll
                for (int g = 0; g < 3; ++g) {
                    uint2 bh = *(const uint2*)&s_Bh[((g * 64 + kc) * 32 + lane) * 2];
                    uint2 bl = *(const uint2*)&s_Bl[((g * 64 + kc) * 32 + lane) * 2];
                    mma_bf16(acc[0][g], (const uint32_t*)&ah0, (const uint32_t*)&bh);
                    mma_bf16(acc[0][g], (const uint32_t*)&al0, (const uint32_t*)&bh);
                    mma_bf16(acc[0][g], (const uint32_t*)&ah0, (const uint32_t*)&bl);
                    mma_bf16(acc[1][g], (const uint32_t*)&ah1, (const uint32_t*)&bh);
                    mma_bf16(acc[1][g], (const uint32_t*)&al1, (const uint32_t*)&bh);
                    mma_bf16(acc[1][g], (const uint32_t*)&ah1, (const uint32_t*)&bl);
                }
                if (kc < 63) { ah0 = nah0; ah1 = nah1; al0 = nal0; al1 = nal1; }
            }
            // D -> smem transpose tile [n=24][batch=256]
            #pragma unroll
            for (int i = 0; i < 2; ++i) {
                int mbase = (wid * 2 + i) * 16 + (lane >> 2);
                #pragma unroll
                for (int g = 0; g < 3; ++g) {
                    int n = g * 8 + (lane & 3) * 2;
                    s_D[n * TB + mbase]           = acc[i][g][0];
                    s_D[(n + 1) * TB + mbase]     = acc[i][g][1];
                    s_D[n * TB + mbase + 8]       = acc[i][g][2];
                    s_D[(n + 1) * TB + mbase + 8] = acc[i][g][3];
                }
            }
        }
        __syncthreads();

        // ========== epilogue (thread = batch b) ==========
        {
            float zz[24];
            #pragma unroll
            for (int r = 0; r < 24; ++r)
                zz[r] = s_bg[r] + ((t > 0) ? s_D[r * TB + b] : 0.f);
            const float* xt = &g_xT[t][0][0];
            #pragma unroll
            for (int k = 0; k < TV; ++k) {
                float xv = xt[k * TB + b];
                const float* wr = s_wgx + k * 24;
                #pragma unroll
                for (int r = 0; r < 24; ++r) zz[r] += xv * wr[r];
            }
            float xvo = xt[v * TB + b];
            float jac[8];
            #pragma unroll
            for (int u = 0; u < 8; ++u) jac[u] = s_bj[u] + xvo * s_uu[u];
            if (t > 0) {
                const float* hv = &g_hsT[t - 1][v * TN][0];
                #pragma unroll 8
                for (int m = 0; m < TN; ++m) {
                    float hm = hv[m * TB + b];
                    const float* wr = s_wj + m * 8;
                    #pragma unroll
                    for (int u = 0; u < 8; ++u) jac[u] += hm * wr[u];
                }
            }
            float hval[8];
            float* ho = &g_hsT[t][0][0];
            #pragma unroll
            for (int ul = 0; ul < 8; ++ul) {
                float iv = 1.f / (1.f + expf(-zz[ul]));
                float fv = 1.f / (1.f + expf(-zz[8 + ul]));
                float ov = 1.f / (1.f + expf(-zz[16 + ul]));
                float jv = tanhf(jac[ul]);
                float cn = cc[ul] * fv + iv * jv;
                cc[ul] = cn;
                hval[ul] = ov * tanhf(cn);
                ho[(size_t)(g0 + ul) * TB + b] = hval[ul];
            }
            #pragma unroll
            for (int p = 0; p < 4; ++p) {
                float v0 = hval[2 * p], v1 = hval[2 * p + 1];
                __nv_bfloat16 h0 = __float2bfloat16(v0), h1 = __float2bfloat16(v1);
                float q0 = v0 - __bfloat162float(h0), q1 = v1 - __bfloat162float(h1);
                __nv_bfloat162 ph = { h0, h1 };
                size_t idx = ((size_t)(kc_e * 16 + mt_e) * 32 + lane_e + p) * 4 + reg_e;
                g_hA_hi[idx] = *reinterpret_cast<uint32_t*>(&ph);
                g_hA_lo[idx] = pack_bf(q0, q1);
            }
        }

        // single grid barrier per step (h + fragments ready)
        __syncthreads();
        if (tid == 0) {
            __threadfence(); atomicAdd(&g_bar, 1u);
            unsigned target = (unsigned)(t + 1) * NCTA;
            while (*((volatile unsigned*)&g_bar) < target) { }
            __threadfence();
        }
        __syncthreads();
    }
}

__global__ void k_alphaA(const float* __restrict__ Fa, const float* __restrict__ Fab) {
    __shared__ float fa[TN]; __shared__ float fabv;
    int v = blockIdx.x, t0 = blockIdx.y * 8, b = threadIdx.x;
    if (threadIdx.x < TN) fa[threadIdx.x] = Fa[v * TN + threadIdx.x];
    if (threadIdx.x == 0) fabv = Fab[v];
    __syncthreads();
    for (int t = t0; t < t0 + 8; ++t) {
        const float* hr = &g_hsT[t][v * TN][0];
        float ap = fabv;
        #pragma unroll 8
        for (int n = 0; n < TN; ++n) ap += hr[n * TB + b] * fa[n];
        g_aunT[t][v][b] = expf(tanhf(ap));
    }
}

__global__ void k_alphaInv() {
    int v = blockIdx.x, b = threadIdx.x;
    float s = 0.f;
    for (int t = 0; t < TT; ++t) s += g_aunT[t][v][b];
    g_inv[v][b] = 1.f / s;
}

__global__ void k_gn() {
    int v = blockIdx.x, nc = blockIdx.y * 2, b = threadIdx.x;
    float a0 = 0.f, a1 = 0.f;
    for (int t = 0; t < TT; ++t) {
        float au = g_aunT[t][v][b];
        const float* hr = &g_hsT[t][v * TN + nc][0];
        a0 += au * hr[0 * TB + b];
        a1 += au * hr[1 * TB + b];
    }
    float inv = g_inv[v][b];
    g_gT[v * TN + nc + 0][b] = a0 * inv;
    g_gT[v * TN + nc + 1][b] = a1 * inv;
}

__global__ void k_alphaOut(float* __restrict__ out) {
    int t = blockIdx.x, b = threadIdx.x;
    float* ao = out + TB;
    #pragma unroll
    for (int v = 0; v < TV; ++v)
        ao[((size_t)b * TT + t) * TV + v] = g_aunT[t][v][b] * g_inv[v][b];
}

__global__ void k_final(const float* __restrict__ Fbw, const float* __restrict__ Fbb,
                        const float* __restrict__ Phw, const float* __restrict__ Phb,
                        float* __restrict__ out) {
    __shared__ float phi[2 * TN], fbw[2 * TN];
    __shared__ float phib, fbb;
    int b = threadIdx.x;
    if (threadIdx.x < 2 * TN) { phi[threadIdx.x] = Phw[threadIdx.x]; fbw[threadIdx.x] = Fbw[threadIdx.x]; }
    if (threadIdx.x == 0) { phib = Phb[0]; fbb = Fbb[0]; }
    __syncthreads();
    float mu[TV], bu[TV], bs = 0.f;
    #pragma unroll
    for (int v = 0; v < TV; ++v) {
        const float* gr = &g_gT[v * TN][0];
        const float* hr = &g_hsT[TT - 1][v * TN][0];
        float m_ = phib, p_ = fbb;
        #pragma unroll 8
        for (int n = 0; n < TN; ++n) {
            float gv = gr[n * TB + b], hv = hr[n * TB + b];
            m_ += gv * phi[n] + hv * phi[TN + n];
            p_ += gv * fbw[n] + hv * fbw[TN + n];
        }
        mu[v] = m_;
        float e = expf(tanhf(p_));
        bu[v] = e; bs += e;
    }
    float ib = 1.f / bs, mean = 0.f;
    float* bout = out + TB + (size_t)TB * TT * TV;
    #pragma unroll
    for (int v = 0; v < TV; ++v) {
        float be = bu[v] * ib;
        mean += be * mu[v];
        bout[(size_t)b * TV + v] = be;
    }
    out[b] = mean;
}

extern "C" void kernel_launch(void* const* d_in, const int* in_sizes, int n_in,
                              void* d_out, int out_size) {
    const float* x    = (const float*)d_in[0];
    const float* U_j  = (const float*)d_in[1];
    const float* W_j  = (const float*)d_in[2];
    const float* b_j  = (const float*)d_in[3];
    const float* Wi   = (const float*)d_in[4];
    const float* bi   = (const float*)d_in[5];
    const float* Wf   = (const float*)d_in[6];
    const float* bf   = (const float*)d_in[7];
    const float* Wo   = (const float*)d_in[8];
    const float* bo   = (const float*)d_in[9];
    const float* Fa   = (const float*)d_in[10];
    const float* Fab  = (const float*)d_in[11];
    const float* Fbw  = (const float*)d_in[12];
    const float* Fbb  = (const float*)d_in[13];
    const float* Phw  = (const float*)d_in[14];
    const float* Phb  = (const float*)d_in[15];
    float* out = (float*)d_out;

    static const int SMEM = 24576 * 4 + 24 * TB * 4;  // B frags + D tile = 122880 B
    cudaFuncSetAttribute(k_recur, cudaFuncAttributeMaxDynamicSharedMemorySize, SMEM);

    k_xT<<<TT * TV, TB>>>(x);
    k_wfrag<<<dim3(384, 64), 64>>>(Wi, Wf, Wo);
    k_recur<<<NCTA, RTHREADS, SMEM>>>(U_j, W_j, b_j, Wi, bi, Wf, bf, Wo, bo);
    k_alphaA<<<dim3(TV, 25), TB>>>(Fa, Fab);
    k_alphaInv<<<TV, TB>>>();
    k_gn<<<dim3(TV, 32), TB>>>();
    k_alphaOut<<<TT, TB>>>(out);
    k_final<<<1, TB>>>(Fbw, Fbb, Phw, Phb, out);
}